// round 17
// baseline (speedup 1.0000x reference)
#include <cuda_runtime.h>
#include <cuda_fp16.h>
#include <cstdint>

#define BATCH   16384
#define IN_DIM  4096
#define OUT_DIM 64
#define BM      64
#define XCH     32                 // x-cols per superchunk
#define KCH     96                 // feature halfs per superchunk
#define NCH2    (IN_DIM / XCH)     // 128 superchunks
#define NS      6                  // m16n8k16 k-steps per superchunk
#define THREADS 384

#define A_ROW_W  52                // words per A row: 48 data (96 halfs) + 4 pad
#define A_BUF_W  (BM * A_ROW_W)    // 3328 words
#define B_BUF_W  (NS * 4 * 32 * 4) // 3072 words
#define SMEM_BYTES ((2 * A_BUF_W + 3 * B_BUF_W) * 4)   // 63488 B

// Fragment-ordered fp16 weights, superchunk-major, pair-packed per warp-column:
// word w: reg=w&1, nl=(w>>1)&1, lane=(w>>2)&31, ntp=(w>>7)&3, s=(w>>9)%6, q=(w>>9)/6
// halfs: k_local = 16s + 2*(lane&3) + 8*reg + h ;  n = (ntp*2+nl)*8 + (lane>>2)
__device__ __align__(16) __half2 g_w2[NCH2 * B_BUF_W];

__device__ __forceinline__ float tanh_fast(float v) {
    float o;
    asm("tanh.approx.f32 %0, %1;" : "=f"(o) : "f"(v));
    return o;
}

// Verified cubic B-spline basis (knots [-1,-.5,0,.5,1,(1)]) + silu(tanh form).
__device__ __forceinline__ void kan_features(float xv, float& b0, float& b1, float& si) {
    float xc = fminf(fmaxf(xv, -1.0f), 1.0f);
    float y1 = xc + 1.0f;
    float y2 = fmaxf(xc + 0.5f, 0.0f);
    float y3 = fmaxf(xc, 0.0f);
    float y4 = fmaxf(xc - 0.5f, 0.0f);
    float c1 = y1 * y1 * y1;
    float c2 = y2 * y2 * y2;
    float c3 = y3 * y3 * y3;
    float c4 = y4 * y4 * y4;
    const float k43  = 1.3333333333333333f;
    const float k163 = 5.3333333333333333f;
    b0 = fmaf(k43, c1, fmaf(-k163, c2, fmaf(8.0f, c3, -k163 * c4)));
    b1 = fmaf(k43, c2, fmaf(-6.0f, c3, 12.0f * c4));
    float xh = 0.5f * xv;
    si = fmaf(xh, tanh_fast(xh), xh);    // x*sigmoid(x) = 0.5x(1+tanh(x/2))
}

__global__ void prep_weights_kernel(const float* __restrict__ c,
                                    const float* __restrict__ ws,
                                    const float* __restrict__ wb) {
    int w = blockIdx.x * blockDim.x + threadIdx.x;
    if (w >= NCH2 * B_BUF_W) return;
    int reg  = w & 1;
    int nl   = (w >> 1) & 1;
    int lane = (w >> 2) & 31;
    int ntp  = (w >> 7) & 3;
    int sq   = w >> 9;
    int s    = sq % 6;
    int q    = sq / 6;
    int t = lane & 3, g = lane >> 2;
    int n = (ntp * 2 + nl) * 8 + g;
    float v[2];
#pragma unroll
    for (int h = 0; h < 2; h++) {
        int kl = 16 * s + 2 * t + 8 * reg + h;
        int kg = q * KCH + kl;
        int i  = kg / 3, f = kg - 3 * i;
        int ij = i * OUT_DIM + n;
        v[h] = (f == 0) ? c[ij * 2] * ws[ij]
             : (f == 1) ? c[ij * 2 + 1] * ws[ij]
                        : wb[ij];
    }
    g_w2[w] = __floats2half2_rn(v[0], v[1]);
}

__device__ __forceinline__ void mma_f16(float* cc, uint32_t a0, uint32_t a1,
                                        uint32_t a2, uint32_t a3,
                                        uint32_t b0, uint32_t b1) {
    asm volatile("mma.sync.aligned.m16n8k16.row.col.f32.f16.f16.f32 "
                 "{%0,%1,%2,%3}, {%4,%5,%6,%7}, {%8,%9}, {%0,%1,%2,%3};"
                 : "+f"(cc[0]), "+f"(cc[1]), "+f"(cc[2]), "+f"(cc[3])
                 : "r"(a0), "r"(a1), "r"(a2), "r"(a3), "r"(b0), "r"(b1));
}

__device__ __forceinline__ void ldmatrix_x4(uint32_t& a0, uint32_t& a1,
                                            uint32_t& a2, uint32_t& a3, uint32_t addr) {
    asm volatile("ldmatrix.sync.aligned.m8n8.x4.shared.b16 {%0,%1,%2,%3}, [%4];"
                 : "=r"(a0), "=r"(a1), "=r"(a2), "=r"(a3) : "r"(addr));
}

__device__ __forceinline__ void cp_async16(uint32_t dst, const void* src) {
    asm volatile("cp.async.cg.shared.global [%0], [%1], 16;"
                 :: "r"(dst), "l"(__cvta_generic_to_global(src)) : "memory");
}

__device__ __forceinline__ uint32_t smem_u32(const void* p) {
    uint32_t a;
    asm("{ .reg .u64 t; cvta.to.shared.u64 t, %1; cvt.u32.u64 %0, t; }" : "=r"(a) : "l"(p));
    return a;
}

// Features for 2 x-values (6 halfs = 3 words) -> 3x STS.32.
__device__ __forceinline__ void write_feat2(uint32_t* dst, float2 v) {
    float b0a, b1a, sa, b0b, b1b, sb;
    kan_features(v.x, b0a, b1a, sa);
    kan_features(v.y, b0b, b1b, sb);
    __half2 h0 = __floats2half2_rn(b0a, b1a);
    __half2 h1 = __floats2half2_rn(sa, b0b);
    __half2 h2 = __floats2half2_rn(b1b, sb);
    dst[0] = *(uint32_t*)&h0;
    dst[1] = *(uint32_t*)&h1;
    dst[2] = *(uint32_t*)&h2;
}

// copy one B superchunk (12288 B) with 384 threads: 2x cp.async.16 each
__device__ __forceinline__ void copy_B(uint32_t dstBase, const char* src, int tid) {
    cp_async16(dstBase + tid * 16,        src + tid * 16);
    cp_async16(dstBase + tid * 16 + 6144, src + tid * 16 + 6144);
}

__global__ __launch_bounds__(THREADS, 2)
void kan_main_kernel(const float* __restrict__ x, float* __restrict__ out) {
    extern __shared__ uint32_t smw[];
    uint32_t* Asm = smw;                       // [2][A_BUF_W]  row-major A
    uint32_t* Bsm = smw + 2 * A_BUF_W;         // [3][B_BUF_W]

    const int tid  = threadIdx.x;
    const int lane = tid & 31;
    const int wid  = tid >> 5;                 // 0..11
    const bool isProd = (wid >= 4);

    // ---- consumer MMA role (warps 0-3): 32x32 output tile each ----
    const int wr = wid & 1;
    const int wc = (wid >> 1) & 1;
    const int g  = lane >> 2;
    const int t  = lane & 3;
    const uint32_t lrow = wr * 32 + (lane & 15);
    const uint32_t lcol = (lane >> 4) * 4;

    // ---- feature role: 2-eval units (row, hg), hg covers x-cols [2hg, 2hg+2)
    // consumers (tid 0..127):   2 units at rows (tid>>4) + 8k,  k=0,1  (rows 0-15)
    // producers (tid 128..383): 3 units at rows 16+(p>>4)+16k, k=0..2 (rows 16-63)
    const int fid  = isProd ? (tid - 128) : tid;
    const int hg   = fid & 15;
    const int R0   = isProd ? (16 + (fid >> 4)) : (fid >> 4);
    const int NU   = isProd ? 3 : 2;
    const size_t rstep = (size_t)(isProd ? 16 : 8) * IN_DIM;
    const int rstepA   = (isProd ? 16 : 8) * A_ROW_W;
    const float* xbase = x + (size_t)(blockIdx.x * BM + R0) * IN_DIM + 2 * hg;

    const uint32_t AsAddr = smem_u32(Asm);
    const uint32_t BsAddr = smem_u32(Bsm);
    uint32_t* Afw = Asm + R0 * A_ROW_W + 3 * hg;

    float cacc[2][4][4];
#pragma unroll
    for (int mt = 0; mt < 2; mt++)
#pragma unroll
        for (int j = 0; j < 4; j++)
#pragma unroll
            for (int r = 0; r < 4; r++) cacc[mt][j][r] = 0.0f;

    // ---- prologue: B(0), B(1) via cp.async (all threads) ----
#pragma unroll
    for (int pc = 0; pc < 2; pc++) {
        copy_B(BsAddr + pc * B_BUF_W * 4,
               (const char*)g_w2 + (size_t)pc * B_BUF_W * 4, tid);
        asm volatile("cp.async.commit_group;" ::: "memory");
    }

    // ---- features(0) + stage x(1) ----
    float2 xa[3];
#pragma unroll
    for (int k = 0; k < 3; k++) {
        if (k < NU) {
            write_feat2(Afw + k * rstepA, *(const float2*)(xbase + k * rstep));
            xa[k] = *(const float2*)(xbase + k * rstep + XCH);
        }
    }

    for (int ch = 0; ch < NCH2; ch++) {
        const int b  = ch & 1;
        const int b3 = ch % 3;

        asm volatile("cp.async.wait_group 1;" ::: "memory");
        __syncthreads();   // publish features(ch) in A[b] and B(ch) in Bsm[b3]

        // all threads: issue B(ch+2) into buf (ch+2)%3 (readers retired pre-barrier)
        {
            int nc2 = ch + 2 < NCH2 ? ch + 2 : NCH2 - 1;
            copy_B(BsAddr + ((ch + 2) % 3) * B_BUF_W * 4,
                   (const char*)g_w2 + (size_t)nc2 * B_BUF_W * 4, tid);
            asm volatile("cp.async.commit_group;" ::: "memory");
        }

        const int nc = ch + 2 < NCH2 ? ch + 2 : NCH2 - 1;
        uint32_t* Adst = Afw + (b ^ 1) * A_BUF_W;

        if (!isProd) {
            // ---- consumers: MMA(ch), then 2 feature units for ch+1 ----
            const uint32_t abase = AsAddr + b * A_BUF_W * 4 + (lrow * A_ROW_W + lcol) * 4;
            const uint32_t* Bb = Bsm + b3 * B_BUF_W;
#pragma unroll
            for (int s = 0; s < NS; s++) {
                uint4 bv0 = *(const uint4*)(Bb + ((s * 4 + wc * 2 + 0) * 32 + lane) * 4);
                uint4 bv1 = *(const uint4*)(Bb + ((s * 4 + wc * 2 + 1) * 32 + lane) * 4);
#pragma unroll
                for (int mt = 0; mt < 2; mt++) {
                    uint32_t a0, a1, a2, a3;
                    ldmatrix_x4(a0, a1, a2, a3, abase + mt * (16 * A_ROW_W * 4) + s * 32);
                    mma_f16(cacc[mt][0], a0, a1, a2, a3, bv0.x, bv0.y);
                    mma_f16(cacc[mt][1], a0, a1, a2, a3, bv0.z, bv0.w);
                    mma_f16(cacc[mt][2], a0, a1, a2, a3, bv1.x, bv1.y);
                    mma_f16(cacc[mt][3], a0, a1, a2, a3, bv1.z, bv1.w);
                }
            }
#pragma unroll
            for (int k = 0; k < 2; k++) {
                write_feat2(Adst + k * rstepA, xa[k]);
                xa[k] = *(const float2*)(xbase + k * rstep + (size_t)nc * XCH);
            }
        } else {
            // ---- producers: 3 feature units for ch+1; stage x(ch+2) ----
#pragma unroll
            for (int k = 0; k < 3; k++) {
                write_feat2(Adst + k * rstepA, xa[k]);
                xa[k] = *(const float2*)(xbase + k * rstep + (size_t)nc * XCH);
            }
        }
    }

    // ---- epilogue (consumers only) ----
    if (!isProd) {
        const int row0 = blockIdx.x * BM + wr * 32 + g;
#pragma unroll
        for (int mt = 0; mt < 2; mt++) {
#pragma unroll
            for (int j = 0; j < 4; j++) {
                int rA = row0 + mt * 16;
                int cA = wc * 32 + j * 8 + 2 * t;
                *(float2*)(out + (size_t)rA * OUT_DIM + cA) =
                    make_float2(cacc[mt][j][0], cacc[mt][j][1]);
                *(float2*)(out + (size_t)(rA + 8) * OUT_DIM + cA) =
                    make_float2(cacc[mt][j][2], cacc[mt][j][3]);
            }
        }
    }
}

extern "C" void kernel_launch(void* const* d_in, const int* in_sizes, int n_in,
                              void* d_out, int out_size) {
    const float* x  = (const float*)d_in[0];
    const float* c  = (const float*)d_in[1];
    const float* ws = (const float*)d_in[2];
    const float* wb = (const float*)d_in[3];
    float* out = (float*)d_out;

    cudaFuncSetAttribute(kan_main_kernel, cudaFuncAttributeMaxDynamicSharedMemorySize,
                         SMEM_BYTES);

    prep_weights_kernel<<<(NCH2 * B_BUF_W + 255) / 256, 256>>>(c, ws, wb);
    kan_main_kernel<<<BATCH / BM, THREADS, SMEM_BYTES>>>(x, out);
}